// round 1
// baseline (speedup 1.0000x reference)
#include <cuda_runtime.h>
#include <math.h>

#define BDIM 4
#define HH 496
#define WW 496
#define HW (HH * WW)
#define NTOT (BDIM * HW)

__device__ float g_num;
__device__ float g_cnt;

__global__ void zero_k() {
    g_num = 0.0f;
    g_cnt = 0.0f;
}

__device__ __forceinline__ void get_corners(float x, float y, float dx, float dy, float r,
                                            float* cx, float* cy) {
    float s, c;
    sincosf(r, &s, &c);
    const float LX[4] = {0.5f, -0.5f, -0.5f, 0.5f};
    const float LY[4] = {0.5f, 0.5f, -0.5f, -0.5f};
#pragma unroll
    for (int i = 0; i < 4; i++) {
        float lx = LX[i] * dx;
        float ly = LY[i] * dy;
        cx[i] = x + c * lx - s * ly;
        cy[i] = y + s * lx + c * ly;
    }
}

__global__ void __launch_bounds__(256) iou_k(const float* __restrict__ iou_pred,
                                             const int* __restrict__ mask,
                                             const float* __restrict__ box_pred,
                                             const float* __restrict__ box_gt) {
    int n = blockIdx.x * blockDim.x + threadIdx.x;
    float lnum = 0.0f;
    float lcnt = 0.0f;

    if (n < NTOT) {
        float m = (float)mask[n];
        if (m != 0.0f) {
            int b = n / HW;
            int hw = n - b * HW;

            // box_pred layout: [B, 7, H, W]
            const float* bp = box_pred + (size_t)b * 7 * HW + hw;
            float pa[7];
#pragma unroll
            for (int c = 0; c < 7; c++) pa[c] = __ldg(bp + (size_t)c * HW);

            // box_gt layout: [B, H, W, 7] -> contiguous per element
            const float* bg = box_gt + (size_t)n * 7;
            float pb[7];
#pragma unroll
            for (int c = 0; c < 7; c++) pb[c] = __ldg(bg + c);

            float ax[4], ay[4], bx[4], by[4];
            get_corners(pa[0], pa[1], pa[3], pa[4], pa[6], ax, ay);
            get_corners(pb[0], pb[1], pb[3], pb[4], pb[6], bx, by);

            // Sutherland-Hodgman: clip quad A by the 4 CCW edges of quad B.
            float px[8], py[8];
            int cnt = 4;
#pragma unroll
            for (int i = 0; i < 4; i++) { px[i] = ax[i]; py[i] = ay[i]; }

#pragma unroll
            for (int e = 0; e < 4; e++) {
                float a0x = bx[e], a0y = by[e];
                float a1x = bx[(e + 1) & 3], a1y = by[(e + 1) & 3];
                float ex = a1x - a0x, ey = a1y - a0y;

                float qx[8], qy[8];
                int mm = 0;
                for (int i = 0; i < cnt; i++) {
                    int j = (i + 1 == cnt) ? 0 : i + 1;
                    float cx0 = px[i], cy0 = py[i];
                    float cx1 = px[j], cy1 = py[j];
                    float dc = ex * (cy0 - a0y) - ey * (cx0 - a0x);
                    float dn = ex * (cy1 - a0y) - ey * (cx1 - a0x);
                    bool inc = dc >= 0.0f;
                    bool inn = dn >= 0.0f;
                    if (inc && mm < 8) {
                        qx[mm] = cx0; qy[mm] = cy0; mm++;
                    }
                    if ((inc != inn) && mm < 8) {
                        float den = dc - dn;
                        float t = dc / (fabsf(den) < 1e-9f ? 1.0f : den);
                        qx[mm] = cx0 + t * (cx1 - cx0);
                        qy[mm] = cy0 + t * (cy1 - cy0);
                        mm++;
                    }
                }
                cnt = mm;
#pragma unroll
                for (int i = 0; i < 8; i++) {
                    px[i] = (i < mm) ? qx[i] : 0.0f;
                    py[i] = (i < mm) ? qy[i] : 0.0f;
                }
            }

            // Shoelace area of the clipped polygon
            float area2 = 0.0f;
            for (int i = 0; i < cnt; i++) {
                int j = (i + 1 == cnt) ? 0 : i + 1;
                area2 += px[i] * py[j] - px[j] * py[i];
            }
            float inter_bev = 0.5f * fabsf(area2);

            // z overlap
            float za0 = pa[2] - 0.5f * pa[5], za1 = pa[2] + 0.5f * pa[5];
            float zb0 = pb[2] - 0.5f * pb[5], zb1 = pb[2] + 0.5f * pb[5];
            float zo = fmaxf(fminf(za1, zb1) - fmaxf(za0, zb0), 0.0f);

            float inter_vol = inter_bev * zo;
            float vol_a = pa[3] * pa[4] * pa[5];
            float vol_b = pb[3] * pb[4] * pb[5];
            float iou = inter_vol / (vol_a + vol_b - inter_vol + 1e-7f);

            float target = 2.0f * iou - 1.0f;
            lnum = m * fabsf(__ldg(iou_pred + n) - target);
            lcnt = m;
        }
    }

    // Block reduction: warp shuffle -> shared -> one atomic pair per block
#pragma unroll
    for (int off = 16; off > 0; off >>= 1) {
        lnum += __shfl_down_sync(0xffffffff, lnum, off);
        lcnt += __shfl_down_sync(0xffffffff, lcnt, off);
    }
    __shared__ float snum[8], scnt[8];
    int lane = threadIdx.x & 31;
    int w = threadIdx.x >> 5;
    if (lane == 0) { snum[w] = lnum; scnt[w] = lcnt; }
    __syncthreads();
    if (w == 0) {
        lnum = (lane < 8) ? snum[lane] : 0.0f;
        lcnt = (lane < 8) ? scnt[lane] : 0.0f;
#pragma unroll
        for (int off = 4; off > 0; off >>= 1) {
            lnum += __shfl_down_sync(0xffffffff, lnum, off);
            lcnt += __shfl_down_sync(0xffffffff, lcnt, off);
        }
        if (lane == 0) {
            atomicAdd(&g_num, lnum);
            atomicAdd(&g_cnt, lcnt);
        }
    }
}

__global__ void fin_k(float* out) {
    out[0] = g_num / (g_cnt + 1e-4f);
}

extern "C" void kernel_launch(void* const* d_in, const int* in_sizes, int n_in,
                              void* d_out, int out_size) {
    const float* iou_pred = (const float*)d_in[0];
    const int* mask = (const int*)d_in[1];
    // d_in[2] = ind (unused by the layer)
    const float* box_pred = (const float*)d_in[3];
    const float* box_gt = (const float*)d_in[4];
    float* out = (float*)d_out;

    zero_k<<<1, 1>>>();
    int threads = 256;
    int blocks = (NTOT + threads - 1) / threads;
    iou_k<<<blocks, threads>>>(iou_pred, mask, box_pred, box_gt);
    fin_k<<<1, 1>>>(out);
}

// round 2
// speedup vs baseline: 2.3608x; 2.3608x over previous
#include <cuda_runtime.h>
#include <math.h>

#define HH 496
#define WW 496
#define HW (HH * WW)
#define BDIM 4
#define NTOT (BDIM * HW)
#define TPB 256
#define NBLK (NTOT / TPB)   // 984064 / 256 = 3844 exactly

__device__ float g_part[2 * NBLK];

// Signed distance of point p to halfplane "left of edge q[j] -> q[j+1]":
// d = ex*(py - qy) - ey*(px - qx) = ex*py - ey*px + (ey*qx - ex*qy)
__device__ __forceinline__ void build_dist(const float* qx, const float* qy,
                                           const float* vx, const float* vy,
                                           float D[4][4]) {
#pragma unroll
    for (int j = 0; j < 4; j++) {
        int j1 = (j + 1) & 3;
        float ex = qx[j1] - qx[j];
        float ey = qy[j1] - qy[j];
        float k = ey * qx[j] - ex * qy[j];
#pragma unroll
        for (int i = 0; i < 4; i++) {
            D[i][j] = fmaf(ex, vy[i], fmaf(-ey, vx[i], k));
        }
    }
}

// Sum over edges of polygon v of (t1-t0)*cross(P0, d), where [t0,t1] is the
// parametric interval of the edge inside the other quad (given dist matrix D,
// D[i][j] = signed dist of vertex i to halfplane j; inside = all >= 0).
__device__ __forceinline__ float clip_accum(const float D[4][4],
                                            const float* vx, const float* vy) {
    float acc = 0.0f;
#pragma unroll
    for (int i = 0; i < 4; i++) {
        int i1 = (i + 1) & 3;
        float dx = vx[i1] - vx[i];
        float dy = vy[i1] - vy[i];
        float t0 = 0.0f, t1 = 1.0f;
#pragma unroll
        for (int j = 0; j < 4; j++) {
            float dc = D[i][j];
            float dn = D[i1][j];
            float den = dn - dc;
            float t = __fdividef(-dc, den);
            float tlo = (den > 0.0f) ? t : 0.0f;   // entering constraint
            float thi = (den < 0.0f) ? t : 1.0f;   // leaving constraint
            t0 = fmaxf(t0, tlo);
            t1 = fminf(t1, thi);
            // parallel edge fully outside -> empty
            t1 = (den == 0.0f && dc < 0.0f) ? -1e30f : t1;
        }
        float cr = vx[i] * dy - vy[i] * dx;
        acc = fmaf(fmaxf(t1 - t0, 0.0f), cr, acc);
    }
    return acc;
}

__device__ __forceinline__ void get_corners(float cx0, float cy0, float dx, float dy,
                                            float s, float c, float* cx, float* cy) {
    const float LX[4] = {0.5f, -0.5f, -0.5f, 0.5f};
    const float LY[4] = {0.5f, 0.5f, -0.5f, -0.5f};
#pragma unroll
    for (int i = 0; i < 4; i++) {
        float lx = LX[i] * dx;
        float ly = LY[i] * dy;
        cx[i] = cx0 + c * lx - s * ly;
        cy[i] = cy0 + s * lx + c * ly;
    }
}

__global__ void __launch_bounds__(TPB) iou_k(const float* __restrict__ iou_pred,
                                             const int* __restrict__ mask,
                                             const float* __restrict__ box_pred,
                                             const float* __restrict__ box_gt) {
    int n = blockIdx.x * TPB + threadIdx.x;
    int b = n / HW;
    int hw = n - b * HW;

    // Issue all loads up front for MLP.
    int m = __ldg(mask + n);
    float ip = __ldg(iou_pred + n);

    const float* bp = box_pred + (size_t)b * 7 * HW + hw;   // [B,7,H,W]
    float pa[7];
#pragma unroll
    for (int c = 0; c < 7; c++) pa[c] = __ldg(bp + (size_t)c * HW);

    const float* bg = box_gt + (size_t)n * 7;               // [B,H,W,7]
    float pb[7];
#pragma unroll
    for (int c = 0; c < 7; c++) pb[c] = __ldg(bg + c);

    float lnum = 0.0f, lcnt = 0.0f;
    if (m != 0) {
        float sa, ca, sb, cb;
        __sincosf(pa[6], &sa, &ca);
        __sincosf(pb[6], &sb, &cb);

        // Center everything on box A for fp32 hygiene.
        float ax[4], ay[4], bx[4], by[4];
        get_corners(0.0f, 0.0f, pa[3], pa[4], sa, ca, ax, ay);
        get_corners(pb[0] - pa[0], pb[1] - pa[1], pb[3], pb[4], sb, cb, bx, by);

        float DA[4][4];   // A-vertex i vs B-halfplane j
        float DB[4][4];   // B-vertex j vs A-halfplane i
        build_dist(bx, by, ax, ay, DA);
        build_dist(ax, ay, bx, by, DB);

        float acc = clip_accum(DA, ax, ay) + clip_accum(DB, bx, by);
        float inter_bev = 0.5f * fabsf(acc);

        float za0 = pa[2] - 0.5f * pa[5], za1 = pa[2] + 0.5f * pa[5];
        float zb0 = pb[2] - 0.5f * pb[5], zb1 = pb[2] + 0.5f * pb[5];
        float zo = fmaxf(fminf(za1, zb1) - fmaxf(za0, zb0), 0.0f);

        float inter_vol = inter_bev * zo;
        float vol_a = pa[3] * pa[4] * pa[5];
        float vol_b = pb[3] * pb[4] * pb[5];
        float iou = inter_vol / (vol_a + vol_b - inter_vol + 1e-7f);

        float target = 2.0f * iou - 1.0f;
        lnum = fabsf(ip - target);
        lcnt = 1.0f;
    }

    // Block reduction: warp shuffle -> shared -> per-block partials (deterministic)
#pragma unroll
    for (int off = 16; off > 0; off >>= 1) {
        lnum += __shfl_down_sync(0xffffffff, lnum, off);
        lcnt += __shfl_down_sync(0xffffffff, lcnt, off);
    }
    __shared__ float snum[8], scnt[8];
    int lane = threadIdx.x & 31;
    int w = threadIdx.x >> 5;
    if (lane == 0) { snum[w] = lnum; scnt[w] = lcnt; }
    __syncthreads();
    if (w == 0) {
        lnum = (lane < 8) ? snum[lane] : 0.0f;
        lcnt = (lane < 8) ? scnt[lane] : 0.0f;
#pragma unroll
        for (int off = 4; off > 0; off >>= 1) {
            lnum += __shfl_down_sync(0xffffffff, lnum, off);
            lcnt += __shfl_down_sync(0xffffffff, lcnt, off);
        }
        if (lane == 0) {
            g_part[blockIdx.x] = lnum;
            g_part[NBLK + blockIdx.x] = lcnt;
        }
    }
}

__global__ void __launch_bounds__(1024) fin_k(float* __restrict__ out) {
    float lnum = 0.0f, lcnt = 0.0f;
    for (int i = threadIdx.x; i < NBLK; i += 1024) {
        lnum += g_part[i];
        lcnt += g_part[NBLK + i];
    }
#pragma unroll
    for (int off = 16; off > 0; off >>= 1) {
        lnum += __shfl_down_sync(0xffffffff, lnum, off);
        lcnt += __shfl_down_sync(0xffffffff, lcnt, off);
    }
    __shared__ float snum[32], scnt[32];
    int lane = threadIdx.x & 31;
    int w = threadIdx.x >> 5;
    if (lane == 0) { snum[w] = lnum; scnt[w] = lcnt; }
    __syncthreads();
    if (w == 0) {
        lnum = (lane < 32) ? snum[lane] : 0.0f;
        lcnt = (lane < 32) ? scnt[lane] : 0.0f;
#pragma unroll
        for (int off = 16; off > 0; off >>= 1) {
            lnum += __shfl_down_sync(0xffffffff, lnum, off);
            lcnt += __shfl_down_sync(0xffffffff, lcnt, off);
        }
        if (lane == 0) out[0] = lnum / (lcnt + 1e-4f);
    }
}

extern "C" void kernel_launch(void* const* d_in, const int* in_sizes, int n_in,
                              void* d_out, int out_size) {
    const float* iou_pred = (const float*)d_in[0];
    const int* mask = (const int*)d_in[1];
    // d_in[2] = ind (unused)
    const float* box_pred = (const float*)d_in[3];
    const float* box_gt = (const float*)d_in[4];
    float* out = (float*)d_out;

    iou_k<<<NBLK, TPB>>>(iou_pred, mask, box_pred, box_gt);
    fin_k<<<1, 1024>>>(out);
}

// round 3
// speedup vs baseline: 2.6516x; 1.1232x over previous
#include <cuda_runtime.h>
#include <math.h>

#define HH 496
#define WW 496
#define HW (HH * WW)
#define BDIM 4
#define NTOT (BDIM * HW)
#define TPB 256
#define BLK_PER_B (HW / TPB)         // 246016/256 = 961 exactly
#define NBLK (BDIM * BLK_PER_B)      // 3844
#define NW (TPB / 32)

__device__ float g_num = 0.0f;
__device__ int g_cnt = 0;
__device__ unsigned int g_done = 0;

// Liang-Barsky interval update for one halfplane.
// D(t) = dc + t*(dn-dc); inside = D >= 0.
__device__ __forceinline__ void upd(float dc, float dn, float& t0, float& t1) {
    float den = dc - dn;
    float t = __fdividef(dc, den);
    if (den < 0.0f)      t0 = fmaxf(t0, t);   // D increasing -> lower bound
    else if (den > 0.0f) t1 = fminf(t1, t);   // D decreasing -> upper bound
    else if (dc < 0.0f)  t1 = -1e30f;         // parallel & outside -> empty
}

__global__ void __launch_bounds__(TPB) iou_k(const float* __restrict__ iou_pred,
                                             const int* __restrict__ mask,
                                             const float* __restrict__ box_pred,
                                             const float* __restrict__ box_gt,
                                             float* __restrict__ out) {
    __shared__ unsigned short s_idx[TPB];
    __shared__ int s_wcnt[NW];
    __shared__ int s_wbase[NW];
    __shared__ float s_red[NW];

    const int tid = threadIdx.x;
    const int lane = tid & 31;
    const int w = tid >> 5;
    const int b = blockIdx.x / BLK_PER_B;     // each block lies in one batch slice
    const int n0 = blockIdx.x * TPB;

    // ---- in-block compaction of active (mask!=0) elements ----
    int m = __ldg(mask + n0 + tid);
    unsigned int ball = __ballot_sync(0xffffffffu, m != 0);
    if (lane == 0) s_wcnt[w] = __popc(ball);
    __syncthreads();
    if (tid < NW) {
        int base = 0;
#pragma unroll
        for (int j = 0; j < NW; j++) base += (j < tid) ? s_wcnt[j] : 0;
        s_wbase[tid] = base;
    }
    __syncthreads();
    const int total = s_wbase[NW - 1] + s_wcnt[NW - 1];
    if (m != 0) {
        int pos = s_wbase[w] + __popc(ball & ((1u << lane) - 1u));
        s_idx[pos] = (unsigned short)tid;
    }
    __syncthreads();

    float lnum = 0.0f;
    if (tid < total) {
        const int ne = n0 + (int)s_idx[tid];
        const int hw = ne - b * HW;

        // box_pred layout [B,7,H,W]; box_gt layout [B,H,W,7]
        const float* bp = box_pred + (size_t)b * 7 * HW + hw;
        float pa0 = __ldg(bp);
        float pa1 = __ldg(bp + HW);
        float pa2 = __ldg(bp + 2 * HW);
        float pa3 = __ldg(bp + 3 * HW);
        float pa4 = __ldg(bp + 4 * HW);
        float pa5 = __ldg(bp + 5 * HW);
        float pa6 = __ldg(bp + 6 * HW);
        const float* bg = box_gt + (size_t)ne * 7;
        float pb0 = __ldg(bg);
        float pb1 = __ldg(bg + 1);
        float pb2 = __ldg(bg + 2);
        float pb3 = __ldg(bg + 3);
        float pb4 = __ldg(bg + 4);
        float pb5 = __ldg(bg + 5);
        float pb6 = __ldg(bg + 6);
        float ip = __ldg(iou_pred + ne);

        // Work in box A's frame: rotate world by -heading_a, center at A.
        float sa, ca, sr, cr;
        __sincosf(pa6, &sa, &ca);
        __sincosf(pb6 - pa6, &sr, &cr);
        float tx = pb0 - pa0, ty = pb1 - pa1;
        float rx = fmaf(ca, tx, sa * ty);
        float ry = fmaf(ca, ty, -sa * tx);

        float hx = 0.5f * pa3, hy = 0.5f * pa4;
        float lx = 0.5f * pb3, ly = 0.5f * pb4;

        // B corners (CCW), A corners are (+-hx, +-hy) implicitly.
        const float SX[4] = {1.f, -1.f, -1.f, 1.f};
        const float SY[4] = {1.f, 1.f, -1.f, -1.f};
        float bxx[4], byy[4];
#pragma unroll
        for (int i = 0; i < 4; i++) {
            float px_ = SX[i] * lx, py_ = SY[i] * ly;
            bxx[i] = rx + cr * px_ - sr * py_;
            byy[i] = ry + sr * px_ + cr * py_;
        }

        // DB[i][j]: B vertex i vs A halfplane j (A axis-aligned -> trivial).
        float DB[4][4];
#pragma unroll
        for (int i = 0; i < 4; i++) {
            DB[i][0] = hy - byy[i];
            DB[i][1] = bxx[i] + hx;
            DB[i][2] = byy[i] + hy;
            DB[i][3] = hx - bxx[i];
        }

        // DA[i][j]: A vertex i vs B halfplane j. k_j doubles as B-edge shoelace cross.
        float DA[4][4], ke[4];
#pragma unroll
        for (int j = 0; j < 4; j++) {
            int j1 = (j + 1) & 3;
            float ex = bxx[j1] - bxx[j];
            float ey = byy[j1] - byy[j];
            float k = fmaf(ey, bxx[j], -ex * byy[j]);
            ke[j] = k;
            float exhy = ex * hy, eyhx = ey * hx;
            float kp = k + exhy, km = k - exhy;
            DA[0][j] = kp - eyhx;
            DA[1][j] = kp + eyhx;
            DA[2][j] = km + eyhx;
            DA[3][j] = km - eyhx;
        }

        // Pass A: A edges clipped by B halfplanes; each cross-term = 2*hx*hy.
        float dtsum = 0.0f;
#pragma unroll
        for (int i = 0; i < 4; i++) {
            int i1 = (i + 1) & 3;
            float t0 = 0.0f, t1 = 1.0f;
#pragma unroll
            for (int j = 0; j < 4; j++) upd(DA[i][j], DA[i1][j], t0, t1);
            dtsum += fmaxf(t1 - t0, 0.0f);
        }
        float acc = dtsum * (2.0f * hx * hy);

        // Pass B: B edges clipped by A halfplanes; cross-term = ke[j].
#pragma unroll
        for (int j = 0; j < 4; j++) {
            int j1 = (j + 1) & 3;
            float t0 = 0.0f, t1 = 1.0f;
#pragma unroll
            for (int i = 0; i < 4; i++) upd(DB[j][i], DB[j1][i], t0, t1);
            acc = fmaf(fmaxf(t1 - t0, 0.0f), ke[j], acc);
        }

        float inter_bev = 0.5f * fabsf(acc);

        float za0 = pa2 - 0.5f * pa5, za1 = pa2 + 0.5f * pa5;
        float zb0 = pb2 - 0.5f * pb5, zb1 = pb2 + 0.5f * pb5;
        float zo = fmaxf(fminf(za1, zb1) - fmaxf(za0, zb0), 0.0f);

        float inter_vol = inter_bev * zo;
        float vol_a = pa3 * pa4 * pa5;
        float vol_b = pb3 * pb4 * pb5;
        float iou = inter_vol / (vol_a + vol_b - inter_vol + 1e-7f);

        lnum = fabsf(ip - (2.0f * iou - 1.0f));
    }

    // ---- block reduction (num only; count is exact int 'total') ----
#pragma unroll
    for (int off = 16; off > 0; off >>= 1)
        lnum += __shfl_down_sync(0xffffffffu, lnum, off);
    if (lane == 0) s_red[w] = lnum;
    __syncthreads();
    if (w == 0) {
        lnum = (lane < NW) ? s_red[lane] : 0.0f;
#pragma unroll
        for (int off = NW / 2; off > 0; off >>= 1)
            lnum += __shfl_down_sync(0xffffffffu, lnum, off);
    }

    // ---- last-block finalize (threadfence reduction pattern) ----
    if (tid == 0) {
        atomicAdd(&g_num, lnum);
        atomicAdd(&g_cnt, total);
        __threadfence();
        unsigned int old = atomicAdd(&g_done, 1u);
        if (old == NBLK - 1) {
            __threadfence();
            float num = *((volatile float*)&g_num);
            int cnt = *((volatile int*)&g_cnt);
            out[0] = num / ((float)cnt + 1e-4f);
            g_num = 0.0f;       // reset for next graph replay
            g_cnt = 0;
            g_done = 0u;
        }
    }
}

extern "C" void kernel_launch(void* const* d_in, const int* in_sizes, int n_in,
                              void* d_out, int out_size) {
    const float* iou_pred = (const float*)d_in[0];
    const int* mask = (const int*)d_in[1];
    // d_in[2] = ind (unused)
    const float* box_pred = (const float*)d_in[3];
    const float* box_gt = (const float*)d_in[4];
    float* out = (float*)d_out;

    iou_k<<<NBLK, TPB>>>(iou_pred, mask, box_pred, box_gt, out);
}